// round 13
// baseline (speedup 1.0000x reference)
#include <cuda_runtime.h>
#include <cstdint>

#define BB 4096
#define NN 32
#define HH 128
#define LL 16
#define AA 10
#define HYBN 3
#define NE 62

// output layout: tuple flattened in return order, float32
#define NF_OFF    0
#define ALP_OFF   (BB*NN*17)              // 2228224
#define HLP_OFF   (ALP_OFF + BB)          // 2232320
#define EATTR_OFF (HLP_OFF + BB)          // 2236416
#define EMASK_OFF (EATTR_OFF + BB*NE*4)   // 3252224

// scratch (__device__ global: allocation-free)
__device__ __align__(16) float d_X[BB*HH];

__constant__ float c_maxval[AA] = {4.f,3.f,2.f,1.f,4.f,2.f,6.f,1.f,4.f,4.f};

// ---------------- Threefry-2x32 (exact JAX implementation) ----------------
__host__ __device__ __forceinline__ uint32_t rotl32(uint32_t x, int d) {
    return (x << d) | (x >> (32 - d));
}
__host__ __device__ __forceinline__ void threefry2x32(uint32_t k0, uint32_t k1,
                                                      uint32_t x0, uint32_t x1,
                                                      uint32_t& o0, uint32_t& o1) {
    uint32_t ks2 = k0 ^ k1 ^ 0x1BD11BDAu;
#define TFR(r) { x0 += x1; x1 = rotl32(x1, (r)); x1 ^= x0; }
    x0 += k0; x1 += k1;
    TFR(13) TFR(15) TFR(26) TFR(6)   x0 += k1;  x1 += ks2 + 1u;
    TFR(17) TFR(29) TFR(16) TFR(24)  x0 += ks2; x1 += k0 + 2u;
    TFR(13) TFR(15) TFR(26) TFR(6)   x0 += k0;  x1 += k1 + 3u;
    TFR(17) TFR(29) TFR(16) TFR(24)  x0 += k1;  x1 += ks2 + 4u;
    TFR(13) TFR(15) TFR(26) TFR(6)   x0 += ks2; x1 += k0 + 5u;
#undef TFR
    o0 = x0; o1 = x1;
}

__device__ __forceinline__ uint32_t rbits32(uint32_t k0, uint32_t k1, uint32_t idx) {
    uint32_t o0, o1;
    threefry2x32(k0, k1, 0u, idx, o0, o1);
    return o0 ^ o1;
}

__device__ __forceinline__ float bits_to_u01(uint32_t b) {
    return __uint_as_float((b >> 9) | 0x3f800000u) - 1.0f;
}

__device__ __forceinline__ float gumbel_draw(uint32_t k0, uint32_t k1, uint32_t idx,
                                             float mn, float span) {
    float u = bits_to_u01(rbits32(k0, k1, idx));
    u = fmaxf(mn, __fadd_rn(__fmul_rn(u, span), mn));
    return -logf(-logf(u));
}

// ---------------- packed f32x2 helpers ----------------
__device__ __forceinline__ unsigned long long packf2(float lo, float hi) {
    unsigned long long r;
    asm("mov.b64 %0, {%1, %2};" : "=l"(r) : "f"(lo), "f"(hi));
    return r;
}
__device__ __forceinline__ void unpackf2(unsigned long long v, float& lo, float& hi) {
    asm("mov.b64 {%0, %1}, %2;" : "=f"(lo), "=f"(hi) : "l"(v));
}
__device__ __forceinline__ void ffma2(unsigned long long& acc,
                                      unsigned long long a, unsigned long long b) {
    asm("fma.rn.f32x2 %0, %1, %2, %0;" : "+l"(acc) : "l"(a), "l"(b));
}

// ---------------- MLP chain (node-uniform GAT stack collapsed to [B,H]) ----------------
// 256 threads, 28 rows/block, W read via LDG (L1-cached; no smem fill phase),
// double-buffered x -> ONE barrier per layer.
#define BROWS 28
__global__ void __launch_bounds__(256) mlp_kernel(
    const float* __restrict__ noise, const float* __restrict__ w1,
    const float* __restrict__ b1, const float* __restrict__ gw,
    const float* __restrict__ gb) {
    // pair-interleaved x, double-buffered: buf[(half*7+p)*256 + c*2 + parity]
    __shared__ __align__(16) float xspA[14 * 256];    // 14 KB
    __shared__ __align__(16) float xspB[14 * 256];    // 14 KB
    const int tid = threadIdx.x;
    const int col = tid & 127;
    const int rh = tid >> 7;            // 0 or 1 -> rows rh*14 .. rh*14+13
    const int base = blockIdx.x * BROWS;

    // load input rows (noise) into paired layout (buffer A)
    for (int i = tid; i < BROWS * HH; i += 256) {
        int r = i >> 7, c = i & 127, g = base + r;
        float v = (g < BB) ? noise[g * HH + c] : 0.f;
        int half = (r < 14) ? 0 : 1;
        int lr = (r < 14) ? r : r - 14;
        xspA[(half * 7 + (lr >> 1)) * 256 + c * 2 + (lr & 1)] = v;
    }

    float keep[14];                      // residual carried in registers
    float* xCur = xspA;
    float* xNxt = xspB;
    #pragma unroll 1
    for (int layer = 0; layer <= LL; layer++) {
        const float* Wsrc = (layer == 0) ? w1 : gw + (size_t)(layer - 1) * HH * HH;
        const float* bsrc = (layer == 0) ? b1 : gb + (layer - 1) * HH;
        __syncthreads();   // xCur fully written (prev layer / init)

        const float bias = bsrc[col];
        unsigned long long accp[7];
        #pragma unroll
        for (int p = 0; p < 7; p++) accp[p] = packf2(bias, bias);

        const float* xpb = &xCur[(rh * 7) * 256];
        const float* wcol = Wsrc + col;
        #pragma unroll 2
        for (int k = 0; k < HH; k += 4) {
            float w0 = __ldg(wcol + (k + 0) * HH);
            float w1v = __ldg(wcol + (k + 1) * HH);
            float w2 = __ldg(wcol + (k + 2) * HH);
            float w3 = __ldg(wcol + (k + 3) * HH);
            unsigned long long wp0 = packf2(w0, w0);
            unsigned long long wp1 = packf2(w1v, w1v);
            unsigned long long wp2 = packf2(w2, w2);
            unsigned long long wp3 = packf2(w3, w3);
            #pragma unroll
            for (int p = 0; p < 7; p++) {
                const ulonglong2 xa = *(const ulonglong2*)&xpb[p * 256 + k * 2];
                const ulonglong2 xb = *(const ulonglong2*)&xpb[p * 256 + k * 2 + 4];
                ffma2(accp[p], xa.x, wp0);
                ffma2(accp[p], xa.y, wp1);
                ffma2(accp[p], xb.x, wp2);
                ffma2(accp[p], xb.y, wp3);
            }
        }

        float av[14];
        #pragma unroll
        for (int p = 0; p < 7; p++) unpackf2(accp[p], av[2 * p], av[2 * p + 1]);
        #pragma unroll
        for (int r = 0; r < 14; r++) {
            float v = (layer == 0) ? av[r] : av[r] + keep[r];
            keep[r] = fmaxf(v, 0.f);
        }
        if (layer < LL) {
            // write to the OTHER buffer: no race with current readers
            #pragma unroll
            for (int p = 0; p < 7; p++)
                *(float2*)&xNxt[(rh * 7 + p) * 256 + col * 2] =
                    make_float2(keep[2 * p], keep[2 * p + 1]);
        }
        float* t = xCur; xCur = xNxt; xNxt = t;
    }
    #pragma unroll
    for (int r = 0; r < 14; r++) {
        int g = base + rh * 14 + r;
        if (g < BB) d_X[(size_t)g * HH + col] = keep[r];
    }
}

// ---------------- Heads: 128 threads = 2 batches x 2 warps (R8-exact) ----------------
__global__ void __launch_bounds__(128) heads_kernel(
    const float* __restrict__ w_atom, const float* __restrict__ b_atom,
    const float* __restrict__ w_hyb,  const float* __restrict__ b_hyb,
    const float* __restrict__ w_deg,  const float* __restrict__ b_deg,
    const float* __restrict__ w_chg,  const float* __restrict__ b_chg,
    const float* __restrict__ w_arom, const float* __restrict__ b_arom,
    const float* __restrict__ w_eex,  const float* __restrict__ b_eex,
    const float* __restrict__ w_ety,  const float* __restrict__ b_ety,
    uint32_t a_k0, uint32_t a_k1, uint32_t h_k0, uint32_t h_k1,
    uint32_t r_k0, uint32_t r_k1, uint32_t e_k0, uint32_t e_k1,
    float mn, float span,
    float* __restrict__ out) {
    __shared__ __align__(16) float xvs[2][HH];
    __shared__ __align__(16) float wa[HH * AA];
    __shared__ __align__(16) float wh[HH * HYBN];
    __shared__ __align__(16) float wdg[HH], wcg[HH], wrg[HH];
    __shared__ __align__(16) float wts[136];
    __shared__ __align__(16) float wes[34];
    __shared__ float nfs[2][NN][17];
    __shared__ float wsum[2][2][2];     // [pair][warp][alp/hlp]

    const int tid = threadIdx.x;
    const int wid = tid >> 5;           // 0..3
    const int lane = tid & 31;
    const int pair = wid >> 1;          // batch within block (0/1)
    const int pw = wid & 1;             // warp within pair

    for (int i = tid; i < HH * AA; i += 128) wa[i] = w_atom[i];
    for (int i = tid; i < HH * HYBN; i += 128) wh[i] = w_hyb[i];
    if (tid < HH) { wdg[tid] = w_deg[tid]; wcg[tid] = w_chg[tid]; wrg[tid] = w_arom[tid]; }
    if (tid < 34) wes[tid] = w_eex[tid];
    for (int i = tid; i < 136; i += 128) wts[i] = w_ety[i];
    __syncthreads();   // single block sync: weight staging

    const int b = blockIdx.x * 2 + pair;

    // both warps of a pair redundantly load the full x row
    ((float4*)xvs[pair])[lane] = ((const float4*)(d_X + (size_t)b * HH))[lane];
    __syncwarp();

    // ---- dots: 16 outputs x 2 lanes, 64 k each ----
    const int o = lane >> 1;
    const int part = lane & 1;
    const float* wp; int stride; float bias;
    if (o < AA)       { wp = wa + o;        stride = AA;   bias = b_atom[o]; }
    else if (o < 13)  { wp = wh + (o - 10); stride = HYBN; bias = b_hyb[o - 10]; }
    else if (o == 13) { wp = wdg;           stride = 1;    bias = b_deg[0]; }
    else if (o == 14) { wp = wcg;           stride = 1;    bias = b_chg[0]; }
    else              { wp = wrg;           stride = 1;    bias = b_arom[0]; }
    float acc = 0.f;
    {
        const int k0 = part * 64;
        const float* xp = xvs[pair];
        #pragma unroll 8
        for (int k = 0; k < 64; k++)
            acc = fmaf(xp[k0 + k], wp[(k0 + k) * stride], acc);
    }
    acc += __shfl_xor_sync(0xffffffffu, acc, 1);
    const float logit = acc + bias;

    // gather all logits from even lanes
    float alog[AA], hlog[HYBN];
    #pragma unroll
    for (int a = 0; a < AA; a++) alog[a] = __shfl_sync(0xffffffffu, logit, 2 * a);
    #pragma unroll
    for (int a = 0; a < HYBN; a++) hlog[a] = __shfl_sync(0xffffffffu, logit, 20 + 2 * a);
    const float dlg = __shfl_sync(0xffffffffu, logit, 26);
    const float clg = __shfl_sync(0xffffffffu, logit, 28);
    const float rlg = __shfl_sync(0xffffffffu, logit, 30);
    const float sdeg = 1.f / (1.f + expf(-dlg));
    const float schg = tanhf(clg);
    const float sarom = 1.f / (1.f + expf(-rlg));

    // ---- log-softmax constants (same serial order as R2/R5) ----
    float m = alog[0];
    #pragma unroll
    for (int a = 1; a < AA; a++) m = fmaxf(m, alog[a]);
    float s = 0.f;
    #pragma unroll
    for (int a = 0; a < AA; a++) s += expf(alog[a] - m);
    const float malse_a = m + logf(s);
    float m2 = hlog[0];
    #pragma unroll
    for (int a = 1; a < HYBN; a++) m2 = fmaxf(m2, hlog[a]);
    float s2 = 0.f;
    #pragma unroll
    for (int a = 0; a < HYBN; a++) s2 += expf(hlog[a] - m2);
    const float malse_h = m2 + logf(s2);

    // ---- node phase: 2 lanes per node; warp pw handles nodes pw*16..pw*16+15 ----
    const int n = pw * 16 + (lane >> 1);
    const int h = lane & 1;
    const uint32_t node = (uint32_t)(b * NN + n);

    int ai = h * 5;
    float best = -3.4e38f, alsel = 0.f;
    #pragma unroll
    for (int j = 0; j < 5; j++) {
        int a = h * 5 + j;
        float g = gumbel_draw(a_k0, a_k1, node * AA + a, mn, span);
        float v = alog[a] + g;
        if (v > best) { best = v; ai = a; alsel = alog[a]; }
    }
    {
        float ob = __shfl_xor_sync(0xffffffffu, best, 1);
        int   oi = __shfl_xor_sync(0xffffffffu, ai, 1);
        float oa = __shfl_xor_sync(0xffffffffu, alsel, 1);
        if (ob > best || (ob == best && oi < ai)) { best = ob; ai = oi; alsel = oa; }
    }
    int hi = (h == 0) ? 0 : 2;
    float bh = -3.4e38f, hlsel;
    if (h == 0) {
        hlsel = hlog[0];
        #pragma unroll
        for (int a = 0; a < 2; a++) {
            float g = gumbel_draw(h_k0, h_k1, node * HYBN + a, mn, span);
            float v = hlog[a] + g;
            if (v > bh) { bh = v; hi = a; hlsel = hlog[a]; }
        }
    } else {
        float g = gumbel_draw(h_k0, h_k1, node * HYBN + 2, mn, span);
        bh = hlog[2] + g;
        hlsel = hlog[2];
    }
    {
        float ob = __shfl_xor_sync(0xffffffffu, bh, 1);
        int   oi = __shfl_xor_sync(0xffffffffu, hi, 1);
        float oh2 = __shfl_xor_sync(0xffffffffu, hlsel, 1);
        if (ob > bh || (ob == bh && oi < hi)) { bh = ob; hi = oi; hlsel = oh2; }
    }
    float u = 0.f;
    if (h == 1) u = bits_to_u01(rbits32(r_k0, r_k1, node));
    u = __shfl_xor_sync(0xffffffffu, u, 1);

    float myalp = 0.f, myhlp = 0.f;
    if (h == 0) {
        const float arom = (u < sarom) ? 1.f : 0.f;
        const float val = c_maxval[ai] / 5.0f;
        float* op = out + NF_OFF + (size_t)node * 17;
        #pragma unroll
        for (int f = 0; f < AA; f++) {
            float x = (f == ai) ? 1.f : 0.f;
            nfs[pair][n][f] = x; op[f] = x;
        }
        nfs[pair][n][10] = sdeg;  op[10] = sdeg;
        nfs[pair][n][11] = schg;  op[11] = schg;
        #pragma unroll
        for (int f = 0; f < HYBN; f++) {
            float x = (f == hi) ? 1.f : 0.f;
            nfs[pair][n][12 + f] = x; op[12 + f] = x;
        }
        nfs[pair][n][15] = arom;  op[15] = arom;
        nfs[pair][n][16] = val;   op[16] = val;
        myalp = alsel - malse_a;
        myhlp = hlsel - malse_h;
    }
    #pragma unroll
    for (int off = 16; off > 0; off >>= 1) {
        myalp += __shfl_down_sync(0xffffffffu, myalp, off);
        myhlp += __shfl_down_sync(0xffffffffu, myhlp, off);
    }
    if (lane == 0) { wsum[pair][pw][0] = myalp; wsum[pair][pw][1] = myhlp; }

    // named barrier over this pair's 64 threads (nf + wsum ready)
    asm volatile("bar.sync %0, 64;" :: "r"(1 + pair) : "memory");

    if (pw == 0 && lane == 0) {
        out[ALP_OFF + b] = (wsum[pair][0][0] + wsum[pair][1][0]) / 32.f;
        out[HLP_OFF + b] = (wsum[pair][0][1] + wsum[pair][1][1]) / 32.f;
    }

    // ---- edge phase: 1 edge per lane across the pair's 64 threads ----
    const int e = pw * 32 + lane;
    if (e < NE) {
        const int un = (e < 31) ? e : e - 30;       // eu
        const int vn = (e < 31) ? e + 1 : e - 31;   // ev
        float elog = b_eex[0];
        float tl[4];
        #pragma unroll
        for (int t = 0; t < 4; t++) tl[t] = b_ety[t];
        #pragma unroll
        for (int f = 0; f < 17; f++) {
            float a1 = nfs[pair][un][f];
            float a2 = nfs[pair][vn][f];
            elog = fmaf(a1, wes[f], elog);
            elog = fmaf(a2, wes[17 + f], elog);
            #pragma unroll
            for (int t = 0; t < 4; t++) {
                tl[t] = fmaf(a1, wts[f * 4 + t], tl[t]);
                tl[t] = fmaf(a2, wts[(17 + f) * 4 + t], tl[t]);
            }
        }
        float p = 1.f / (1.f + expf(-elog));
        out[EMASK_OFF + (size_t)b * NE + e] = (p > 0.5f) ? 1.f : 0.f;

        const uint32_t ebase = (uint32_t)(b * NE + e) * 4u;
        int ti = 0; float bt = -1e30f;
        #pragma unroll
        for (int t = 0; t < 4; t++) {
            float g = gumbel_draw(e_k0, e_k1, ebase + t, mn, span);
            float v = tl[t] + g;
            if (v > bt) { bt = v; ti = t; }
        }
        float4 oh;
        oh.x = (ti == 0) ? 1.f : 0.f;
        oh.y = (ti == 1) ? 1.f : 0.f;
        oh.z = (ti == 2) ? 1.f : 0.f;
        oh.w = (ti == 3) ? 1.f : 0.f;
        *(float4*)(out + EATTR_OFF + (size_t)ebase) = oh;
    }
}

// ---------------- launch ----------------
extern "C" void kernel_launch(void* const* d_in, const int* in_sizes, int n_in,
                              void* d_out, int out_size) {
    const float* noise  = (const float*)d_in[0];
    const float* w1     = (const float*)d_in[1];
    const float* b1     = (const float*)d_in[2];
    const float* gat_w  = (const float*)d_in[3];
    const float* gat_b  = (const float*)d_in[4];
    // d_in[5] att_src, d_in[6] att_dst: numerically irrelevant (node-uniform collapse)
    const float* w_atom = (const float*)d_in[7];
    const float* b_atom = (const float*)d_in[8];
    const float* w_hyb  = (const float*)d_in[9];
    const float* b_hyb  = (const float*)d_in[10];
    const float* w_deg  = (const float*)d_in[11];
    const float* b_deg  = (const float*)d_in[12];
    const float* w_chg  = (const float*)d_in[13];
    const float* b_chg  = (const float*)d_in[14];
    const float* w_arom = (const float*)d_in[15];
    const float* b_arom = (const float*)d_in[16];
    const float* w_eex  = (const float*)d_in[17];
    const float* b_eex  = (const float*)d_in[18];
    const float* w_ety  = (const float*)d_in[19];
    const float* b_ety  = (const float*)d_in[20];
    float* out = (float*)d_out;

    // jax.random.key(42) -> (0, 42); partitionable split: sk[i] = threefry(key,(0,i))
    uint32_t sk[4][2];
    for (uint32_t i = 0; i < 4; i++)
        threefry2x32(0u, 42u, 0u, i, sk[i][0], sk[i][1]);

    const float mn = 1e-6f;
    const float mx = (float)(1.0 - 1e-6);
    const float span = mx - mn;

    mlp_kernel<<<(BB + BROWS - 1) / BROWS, 256>>>(noise, w1, b1, gat_w, gat_b);

    heads_kernel<<<BB / 2, 128>>>(w_atom, b_atom, w_hyb, b_hyb, w_deg, b_deg,
                                  w_chg, b_chg, w_arom, b_arom, w_eex, b_eex,
                                  w_ety, b_ety,
                                  sk[0][0], sk[0][1], sk[1][0], sk[1][1],
                                  sk[2][0], sk[2][1], sk[3][0], sk[3][1],
                                  mn, span, out);
}

// round 14
// speedup vs baseline: 1.2034x; 1.2034x over previous
#include <cuda_runtime.h>
#include <cstdint>

#define BB 4096
#define NN 32
#define HH 128
#define LL 16
#define AA 10
#define HYBN 3
#define NE 62

// output layout: tuple flattened in return order, float32
#define NF_OFF    0
#define ALP_OFF   (BB*NN*17)              // 2228224
#define HLP_OFF   (ALP_OFF + BB)          // 2232320
#define EATTR_OFF (HLP_OFF + BB)          // 2236416
#define EMASK_OFF (EATTR_OFF + BB*NE*4)   // 3252224

// scratch (__device__ global: allocation-free)
__device__ __align__(16) float d_X[BB*HH];

__constant__ float c_maxval[AA] = {4.f,3.f,2.f,1.f,4.f,2.f,6.f,1.f,4.f,4.f};

// ---------------- Threefry-2x32 (exact JAX implementation) ----------------
__host__ __device__ __forceinline__ uint32_t rotl32(uint32_t x, int d) {
    return (x << d) | (x >> (32 - d));
}
__host__ __device__ __forceinline__ void threefry2x32(uint32_t k0, uint32_t k1,
                                                      uint32_t x0, uint32_t x1,
                                                      uint32_t& o0, uint32_t& o1) {
    uint32_t ks2 = k0 ^ k1 ^ 0x1BD11BDAu;
#define TFR(r) { x0 += x1; x1 = rotl32(x1, (r)); x1 ^= x0; }
    x0 += k0; x1 += k1;
    TFR(13) TFR(15) TFR(26) TFR(6)   x0 += k1;  x1 += ks2 + 1u;
    TFR(17) TFR(29) TFR(16) TFR(24)  x0 += ks2; x1 += k0 + 2u;
    TFR(13) TFR(15) TFR(26) TFR(6)   x0 += k0;  x1 += k1 + 3u;
    TFR(17) TFR(29) TFR(16) TFR(24)  x0 += k1;  x1 += ks2 + 4u;
    TFR(13) TFR(15) TFR(26) TFR(6)   x0 += ks2; x1 += k0 + 5u;
#undef TFR
    o0 = x0; o1 = x1;
}

__device__ __forceinline__ uint32_t rbits32(uint32_t k0, uint32_t k1, uint32_t idx) {
    uint32_t o0, o1;
    threefry2x32(k0, k1, 0u, idx, o0, o1);
    return o0 ^ o1;
}

__device__ __forceinline__ float bits_to_u01(uint32_t b) {
    return __uint_as_float((b >> 9) | 0x3f800000u) - 1.0f;
}

__device__ __forceinline__ float gumbel_draw(uint32_t k0, uint32_t k1, uint32_t idx,
                                             float mn, float span) {
    float u = bits_to_u01(rbits32(k0, k1, idx));
    u = fmaxf(mn, __fadd_rn(__fmul_rn(u, span), mn));
    return -logf(-logf(u));
}

// ---------------- packed f32x2 helpers ----------------
__device__ __forceinline__ unsigned long long packf2(float lo, float hi) {
    unsigned long long r;
    asm("mov.b64 %0, {%1, %2};" : "=l"(r) : "f"(lo), "f"(hi));
    return r;
}
__device__ __forceinline__ void unpackf2(unsigned long long v, float& lo, float& hi) {
    asm("mov.b64 {%0, %1}, %2;" : "=f"(lo), "=f"(hi) : "l"(v));
}
__device__ __forceinline__ void ffma2(unsigned long long& acc,
                                      unsigned long long a, unsigned long long b) {
    asm("fma.rn.f32x2 %0, %1, %2, %0;" : "+l"(acc) : "l"(a), "l"(b));
}

// ---------------- MLP chain (node-uniform GAT stack collapsed to [B,H]) ----------------
// 256 threads, 28 rows/block. Warp tile r7 x c64: warp w -> row-group rg=w>>1
// (7 rows), col-group cg=w&1 (64 cols); lane handles cols c1=cg*64+lane, c2=c1+32.
// Rows packed as 3 f32x2 pairs + 1 scalar row. Smem-staged W (R12 fill).
#define BROWS 28
__global__ void __launch_bounds__(256) mlp_kernel(
    const float* __restrict__ noise, const float* __restrict__ w1,
    const float* __restrict__ b1, const float* __restrict__ gw,
    const float* __restrict__ gb) {
    __shared__ __align__(16) float Ws[HH * HH];       // 64 KB
    // pair rows: xsp[(rg*3+p)*256 + k*2 + parity], rows (2p,2p+1) of group rg
    __shared__ __align__(16) float xsp[12 * 256];     // 12 KB
    // scalar row (row 6 of each group): xss[rg*128 + k]
    __shared__ __align__(16) float xss[4 * HH];       // 2 KB
    const int tid = threadIdx.x;
    const int lane = tid & 31;
    const int w = tid >> 5;
    const int rg = w >> 1;              // 0..3
    const int cg = w & 1;               // 0..1
    const int c1 = cg * 64 + lane;
    const int c2 = c1 + 32;
    const int base = blockIdx.x * BROWS;

    // load input rows (noise) into grouped layout
    for (int i = tid; i < BROWS * HH; i += 256) {
        int r = i >> 7, c = i & 127, g = base + r;
        float v = (g < BB) ? noise[g * HH + c] : 0.f;
        int rgi = r / 7, rel = r % 7;
        if (rel == 6) xss[rgi * HH + c] = v;
        else xsp[(rgi * 3 + (rel >> 1)) * 256 + c * 2 + (rel & 1)] = v;
    }

    float keep[14];                      // keep[rel*2+ci]
    #pragma unroll 1
    for (int layer = 0; layer <= LL; layer++) {
        const float* Wsrc = (layer == 0) ? w1 : gw + (size_t)(layer - 1) * HH * HH;
        const float* bsrc = (layer == 0) ? b1 : gb + (layer - 1) * HH;
        {
            const float4* wv = (const float4*)Wsrc;
            float4* wd = (float4*)Ws;
            #pragma unroll
            for (int i = 0; i < 16; i++) wd[tid + i * 256] = wv[tid + i * 256];
        }
        __syncthreads();   // Ws ready; xsp/xss stores from previous layer done

        const float bias1 = bsrc[c1];
        const float bias2 = bsrc[c2];
        unsigned long long accp[6];      // [p][ci]
        float acc61, acc62;
        #pragma unroll
        for (int p = 0; p < 3; p++) {
            accp[p * 2 + 0] = packf2(bias1, bias1);
            accp[p * 2 + 1] = packf2(bias2, bias2);
        }
        acc61 = bias1; acc62 = bias2;

        const float* xpb = &xsp[(rg * 3) * 256];
        const float* xsc = &xss[rg * HH];
        #pragma unroll 2
        for (int k = 0; k < HH; k += 4) {
            float wa0 = Ws[(k + 0) * HH + c1];
            float wa1 = Ws[(k + 1) * HH + c1];
            float wa2 = Ws[(k + 2) * HH + c1];
            float wa3 = Ws[(k + 3) * HH + c1];
            float wb0 = Ws[(k + 0) * HH + c2];
            float wb1 = Ws[(k + 1) * HH + c2];
            float wb2 = Ws[(k + 2) * HH + c2];
            float wb3 = Ws[(k + 3) * HH + c2];
            unsigned long long wa0p = packf2(wa0, wa0);
            unsigned long long wa1p = packf2(wa1, wa1);
            unsigned long long wa2p = packf2(wa2, wa2);
            unsigned long long wa3p = packf2(wa3, wa3);
            unsigned long long wb0p = packf2(wb0, wb0);
            unsigned long long wb1p = packf2(wb1, wb1);
            unsigned long long wb2p = packf2(wb2, wb2);
            unsigned long long wb3p = packf2(wb3, wb3);
            #pragma unroll
            for (int p = 0; p < 3; p++) {
                const ulonglong2 xa = *(const ulonglong2*)&xpb[p * 256 + k * 2];
                const ulonglong2 xb = *(const ulonglong2*)&xpb[p * 256 + k * 2 + 4];
                ffma2(accp[p * 2 + 0], xa.x, wa0p);
                ffma2(accp[p * 2 + 0], xa.y, wa1p);
                ffma2(accp[p * 2 + 0], xb.x, wa2p);
                ffma2(accp[p * 2 + 0], xb.y, wa3p);
                ffma2(accp[p * 2 + 1], xa.x, wb0p);
                ffma2(accp[p * 2 + 1], xa.y, wb1p);
                ffma2(accp[p * 2 + 1], xb.x, wb2p);
                ffma2(accp[p * 2 + 1], xb.y, wb3p);
            }
            {
                const float4 xv = *(const float4*)&xsc[k];
                acc61 = fmaf(xv.x, wa0, acc61);
                acc61 = fmaf(xv.y, wa1, acc61);
                acc61 = fmaf(xv.z, wa2, acc61);
                acc61 = fmaf(xv.w, wa3, acc61);
                acc62 = fmaf(xv.x, wb0, acc62);
                acc62 = fmaf(xv.y, wb1, acc62);
                acc62 = fmaf(xv.z, wb2, acc62);
                acc62 = fmaf(xv.w, wb3, acc62);
            }
        }
        __syncthreads();   // all reads of Ws/xsp/xss complete

        float av[14];
        #pragma unroll
        for (int p = 0; p < 3; p++) {
            unpackf2(accp[p * 2 + 0], av[(2 * p) * 2 + 0], av[(2 * p + 1) * 2 + 0]);
            unpackf2(accp[p * 2 + 1], av[(2 * p) * 2 + 1], av[(2 * p + 1) * 2 + 1]);
        }
        av[12] = acc61; av[13] = acc62;
        #pragma unroll
        for (int i = 0; i < 14; i++) {
            float v = (layer == 0) ? av[i] : av[i] + keep[i];
            keep[i] = fmaxf(v, 0.f);
        }
        if (layer < LL) {
            #pragma unroll
            for (int p = 0; p < 3; p++) {
                *(float2*)&xsp[(rg * 3 + p) * 256 + c1 * 2] =
                    make_float2(keep[(2 * p) * 2 + 0], keep[(2 * p + 1) * 2 + 0]);
                *(float2*)&xsp[(rg * 3 + p) * 256 + c2 * 2] =
                    make_float2(keep[(2 * p) * 2 + 1], keep[(2 * p + 1) * 2 + 1]);
            }
            xss[rg * HH + c1] = keep[12];
            xss[rg * HH + c2] = keep[13];
        }
    }
    // final store: rows base + rg*7 + rel, cols c1/c2
    #pragma unroll
    for (int rel = 0; rel < 7; rel++) {
        int g = base + rg * 7 + rel;
        if (g < BB) {
            d_X[(size_t)g * HH + c1] = keep[rel * 2 + 0];
            d_X[(size_t)g * HH + c2] = keep[rel * 2 + 1];
        }
    }
}

// ---------------- Heads: 128 threads = 2 batches x 2 warps (R8-exact) ----------------
__global__ void __launch_bounds__(128) heads_kernel(
    const float* __restrict__ w_atom, const float* __restrict__ b_atom,
    const float* __restrict__ w_hyb,  const float* __restrict__ b_hyb,
    const float* __restrict__ w_deg,  const float* __restrict__ b_deg,
    const float* __restrict__ w_chg,  const float* __restrict__ b_chg,
    const float* __restrict__ w_arom, const float* __restrict__ b_arom,
    const float* __restrict__ w_eex,  const float* __restrict__ b_eex,
    const float* __restrict__ w_ety,  const float* __restrict__ b_ety,
    uint32_t a_k0, uint32_t a_k1, uint32_t h_k0, uint32_t h_k1,
    uint32_t r_k0, uint32_t r_k1, uint32_t e_k0, uint32_t e_k1,
    float mn, float span,
    float* __restrict__ out) {
    __shared__ __align__(16) float xvs[2][HH];
    __shared__ __align__(16) float wa[HH * AA];
    __shared__ __align__(16) float wh[HH * HYBN];
    __shared__ __align__(16) float wdg[HH], wcg[HH], wrg[HH];
    __shared__ __align__(16) float wts[136];
    __shared__ __align__(16) float wes[34];
    __shared__ float nfs[2][NN][17];
    __shared__ float wsum[2][2][2];     // [pair][warp][alp/hlp]

    const int tid = threadIdx.x;
    const int wid = tid >> 5;           // 0..3
    const int lane = tid & 31;
    const int pair = wid >> 1;          // batch within block (0/1)
    const int pw = wid & 1;             // warp within pair

    for (int i = tid; i < HH * AA; i += 128) wa[i] = w_atom[i];
    for (int i = tid; i < HH * HYBN; i += 128) wh[i] = w_hyb[i];
    if (tid < HH) { wdg[tid] = w_deg[tid]; wcg[tid] = w_chg[tid]; wrg[tid] = w_arom[tid]; }
    if (tid < 34) wes[tid] = w_eex[tid];
    for (int i = tid; i < 136; i += 128) wts[i] = w_ety[i];
    __syncthreads();   // single block sync: weight staging

    const int b = blockIdx.x * 2 + pair;

    // both warps of a pair redundantly load the full x row
    ((float4*)xvs[pair])[lane] = ((const float4*)(d_X + (size_t)b * HH))[lane];
    __syncwarp();

    // ---- dots: 16 outputs x 2 lanes, 64 k each ----
    const int o = lane >> 1;
    const int part = lane & 1;
    const float* wp; int stride; float bias;
    if (o < AA)       { wp = wa + o;        stride = AA;   bias = b_atom[o]; }
    else if (o < 13)  { wp = wh + (o - 10); stride = HYBN; bias = b_hyb[o - 10]; }
    else if (o == 13) { wp = wdg;           stride = 1;    bias = b_deg[0]; }
    else if (o == 14) { wp = wcg;           stride = 1;    bias = b_chg[0]; }
    else              { wp = wrg;           stride = 1;    bias = b_arom[0]; }
    float acc = 0.f;
    {
        const int k0 = part * 64;
        const float* xp = xvs[pair];
        #pragma unroll 8
        for (int k = 0; k < 64; k++)
            acc = fmaf(xp[k0 + k], wp[(k0 + k) * stride], acc);
    }
    acc += __shfl_xor_sync(0xffffffffu, acc, 1);
    const float logit = acc + bias;

    // gather all logits from even lanes
    float alog[AA], hlog[HYBN];
    #pragma unroll
    for (int a = 0; a < AA; a++) alog[a] = __shfl_sync(0xffffffffu, logit, 2 * a);
    #pragma unroll
    for (int a = 0; a < HYBN; a++) hlog[a] = __shfl_sync(0xffffffffu, logit, 20 + 2 * a);
    const float dlg = __shfl_sync(0xffffffffu, logit, 26);
    const float clg = __shfl_sync(0xffffffffu, logit, 28);
    const float rlg = __shfl_sync(0xffffffffu, logit, 30);
    const float sdeg = 1.f / (1.f + expf(-dlg));
    const float schg = tanhf(clg);
    const float sarom = 1.f / (1.f + expf(-rlg));

    // ---- log-softmax constants (same serial order as R2/R5) ----
    float m = alog[0];
    #pragma unroll
    for (int a = 1; a < AA; a++) m = fmaxf(m, alog[a]);
    float s = 0.f;
    #pragma unroll
    for (int a = 0; a < AA; a++) s += expf(alog[a] - m);
    const float malse_a = m + logf(s);
    float m2 = hlog[0];
    #pragma unroll
    for (int a = 1; a < HYBN; a++) m2 = fmaxf(m2, hlog[a]);
    float s2 = 0.f;
    #pragma unroll
    for (int a = 0; a < HYBN; a++) s2 += expf(hlog[a] - m2);
    const float malse_h = m2 + logf(s2);

    // ---- node phase: 2 lanes per node; warp pw handles nodes pw*16..pw*16+15 ----
    const int n = pw * 16 + (lane >> 1);
    const int h = lane & 1;
    const uint32_t node = (uint32_t)(b * NN + n);

    int ai = h * 5;
    float best = -3.4e38f, alsel = 0.f;
    #pragma unroll
    for (int j = 0; j < 5; j++) {
        int a = h * 5 + j;
        float g = gumbel_draw(a_k0, a_k1, node * AA + a, mn, span);
        float v = alog[a] + g;
        if (v > best) { best = v; ai = a; alsel = alog[a]; }
    }
    {
        float ob = __shfl_xor_sync(0xffffffffu, best, 1);
        int   oi = __shfl_xor_sync(0xffffffffu, ai, 1);
        float oa = __shfl_xor_sync(0xffffffffu, alsel, 1);
        if (ob > best || (ob == best && oi < ai)) { best = ob; ai = oi; alsel = oa; }
    }
    int hi = (h == 0) ? 0 : 2;
    float bh = -3.4e38f, hlsel;
    if (h == 0) {
        hlsel = hlog[0];
        #pragma unroll
        for (int a = 0; a < 2; a++) {
            float g = gumbel_draw(h_k0, h_k1, node * HYBN + a, mn, span);
            float v = hlog[a] + g;
            if (v > bh) { bh = v; hi = a; hlsel = hlog[a]; }
        }
    } else {
        float g = gumbel_draw(h_k0, h_k1, node * HYBN + 2, mn, span);
        bh = hlog[2] + g;
        hlsel = hlog[2];
    }
    {
        float ob = __shfl_xor_sync(0xffffffffu, bh, 1);
        int   oi = __shfl_xor_sync(0xffffffffu, hi, 1);
        float oh2 = __shfl_xor_sync(0xffffffffu, hlsel, 1);
        if (ob > bh || (ob == bh && oi < hi)) { bh = ob; hi = oi; hlsel = oh2; }
    }
    float u = 0.f;
    if (h == 1) u = bits_to_u01(rbits32(r_k0, r_k1, node));
    u = __shfl_xor_sync(0xffffffffu, u, 1);

    float myalp = 0.f, myhlp = 0.f;
    if (h == 0) {
        const float arom = (u < sarom) ? 1.f : 0.f;
        const float val = c_maxval[ai] / 5.0f;
        float* op = out + NF_OFF + (size_t)node * 17;
        #pragma unroll
        for (int f = 0; f < AA; f++) {
            float x = (f == ai) ? 1.f : 0.f;
            nfs[pair][n][f] = x; op[f] = x;
        }
        nfs[pair][n][10] = sdeg;  op[10] = sdeg;
        nfs[pair][n][11] = schg;  op[11] = schg;
        #pragma unroll
        for (int f = 0; f < HYBN; f++) {
            float x = (f == hi) ? 1.f : 0.f;
            nfs[pair][n][12 + f] = x; op[12 + f] = x;
        }
        nfs[pair][n][15] = arom;  op[15] = arom;
        nfs[pair][n][16] = val;   op[16] = val;
        myalp = alsel - malse_a;
        myhlp = hlsel - malse_h;
    }
    #pragma unroll
    for (int off = 16; off > 0; off >>= 1) {
        myalp += __shfl_down_sync(0xffffffffu, myalp, off);
        myhlp += __shfl_down_sync(0xffffffffu, myhlp, off);
    }
    if (lane == 0) { wsum[pair][pw][0] = myalp; wsum[pair][pw][1] = myhlp; }

    // named barrier over this pair's 64 threads (nf + wsum ready)
    asm volatile("bar.sync %0, 64;" :: "r"(1 + pair) : "memory");

    if (pw == 0 && lane == 0) {
        out[ALP_OFF + b] = (wsum[pair][0][0] + wsum[pair][1][0]) / 32.f;
        out[HLP_OFF + b] = (wsum[pair][0][1] + wsum[pair][1][1]) / 32.f;
    }

    // ---- edge phase: 1 edge per lane across the pair's 64 threads ----
    const int e = pw * 32 + lane;
    if (e < NE) {
        const int un = (e < 31) ? e : e - 30;       // eu
        const int vn = (e < 31) ? e + 1 : e - 31;   // ev
        float elog = b_eex[0];
        float tl[4];
        #pragma unroll
        for (int t = 0; t < 4; t++) tl[t] = b_ety[t];
        #pragma unroll
        for (int f = 0; f < 17; f++) {
            float a1 = nfs[pair][un][f];
            float a2 = nfs[pair][vn][f];
            elog = fmaf(a1, wes[f], elog);
            elog = fmaf(a2, wes[17 + f], elog);
            #pragma unroll
            for (int t = 0; t < 4; t++) {
                tl[t] = fmaf(a1, wts[f * 4 + t], tl[t]);
                tl[t] = fmaf(a2, wts[(17 + f) * 4 + t], tl[t]);
            }
        }
        float p = 1.f / (1.f + expf(-elog));
        out[EMASK_OFF + (size_t)b * NE + e] = (p > 0.5f) ? 1.f : 0.f;

        const uint32_t ebase = (uint32_t)(b * NE + e) * 4u;
        int ti = 0; float bt = -1e30f;
        #pragma unroll
        for (int t = 0; t < 4; t++) {
            float g = gumbel_draw(e_k0, e_k1, ebase + t, mn, span);
            float v = tl[t] + g;
            if (v > bt) { bt = v; ti = t; }
        }
        float4 oh;
        oh.x = (ti == 0) ? 1.f : 0.f;
        oh.y = (ti == 1) ? 1.f : 0.f;
        oh.z = (ti == 2) ? 1.f : 0.f;
        oh.w = (ti == 3) ? 1.f : 0.f;
        *(float4*)(out + EATTR_OFF + (size_t)ebase) = oh;
    }
}

// ---------------- launch ----------------
extern "C" void kernel_launch(void* const* d_in, const int* in_sizes, int n_in,
                              void* d_out, int out_size) {
    const float* noise  = (const float*)d_in[0];
    const float* w1     = (const float*)d_in[1];
    const float* b1     = (const float*)d_in[2];
    const float* gat_w  = (const float*)d_in[3];
    const float* gat_b  = (const float*)d_in[4];
    // d_in[5] att_src, d_in[6] att_dst: numerically irrelevant (node-uniform collapse)
    const float* w_atom = (const float*)d_in[7];
    const float* b_atom = (const float*)d_in[8];
    const float* w_hyb  = (const float*)d_in[9];
    const float* b_hyb  = (const float*)d_in[10];
    const float* w_deg  = (const float*)d_in[11];
    const float* b_deg  = (const float*)d_in[12];
    const float* w_chg  = (const float*)d_in[13];
    const float* b_chg  = (const float*)d_in[14];
    const float* w_arom = (const float*)d_in[15];
    const float* b_arom = (const float*)d_in[16];
    const float* w_eex  = (const float*)d_in[17];
    const float* b_eex  = (const float*)d_in[18];
    const float* w_ety  = (const float*)d_in[19];
    const float* b_ety  = (const float*)d_in[20];
    float* out = (float*)d_out;

    // jax.random.key(42) -> (0, 42); partitionable split: sk[i] = threefry(key,(0,i))
    uint32_t sk[4][2];
    for (uint32_t i = 0; i < 4; i++)
        threefry2x32(0u, 42u, 0u, i, sk[i][0], sk[i][1]);

    const float mn = 1e-6f;
    const float mx = (float)(1.0 - 1e-6);
    const float span = mx - mn;

    mlp_kernel<<<(BB + BROWS - 1) / BROWS, 256>>>(noise, w1, b1, gat_w, gat_b);

    heads_kernel<<<BB / 2, 128>>>(w_atom, b_atom, w_hyb, b_hyb, w_deg, b_deg,
                                  w_chg, b_chg, w_arom, b_arom, w_eex, b_eex,
                                  w_ety, b_ety,
                                  sk[0][0], sk[0][1], sk[1][0], sk[1][1],
                                  sk[2][0], sk[2][1], sk[3][0], sk[3][1],
                                  mn, span, out);
}

// round 15
// speedup vs baseline: 1.2685x; 1.0540x over previous
#include <cuda_runtime.h>
#include <cstdint>

#define BB 4096
#define NN 32
#define HH 128
#define LL 16
#define AA 10
#define HYBN 3
#define NE 62

// output layout: tuple flattened in return order, float32
#define NF_OFF    0
#define ALP_OFF   (BB*NN*17)              // 2228224
#define HLP_OFF   (ALP_OFF + BB)          // 2232320
#define EATTR_OFF (HLP_OFF + BB)          // 2236416
#define EMASK_OFF (EATTR_OFF + BB*NE*4)   // 3252224

// scratch (__device__ global: allocation-free)
__device__ __align__(16) float d_X[BB*HH];

__constant__ float c_maxval[AA] = {4.f,3.f,2.f,1.f,4.f,2.f,6.f,1.f,4.f,4.f};

// ---------------- Threefry-2x32 (exact JAX implementation) ----------------
__host__ __device__ __forceinline__ uint32_t rotl32(uint32_t x, int d) {
    return (x << d) | (x >> (32 - d));
}
__host__ __device__ __forceinline__ void threefry2x32(uint32_t k0, uint32_t k1,
                                                      uint32_t x0, uint32_t x1,
                                                      uint32_t& o0, uint32_t& o1) {
    uint32_t ks2 = k0 ^ k1 ^ 0x1BD11BDAu;
#define TFR(r) { x0 += x1; x1 = rotl32(x1, (r)); x1 ^= x0; }
    x0 += k0; x1 += k1;
    TFR(13) TFR(15) TFR(26) TFR(6)   x0 += k1;  x1 += ks2 + 1u;
    TFR(17) TFR(29) TFR(16) TFR(24)  x0 += ks2; x1 += k0 + 2u;
    TFR(13) TFR(15) TFR(26) TFR(6)   x0 += k0;  x1 += k1 + 3u;
    TFR(17) TFR(29) TFR(16) TFR(24)  x0 += k1;  x1 += ks2 + 4u;
    TFR(13) TFR(15) TFR(26) TFR(6)   x0 += ks2; x1 += k0 + 5u;
#undef TFR
    o0 = x0; o1 = x1;
}

__device__ __forceinline__ uint32_t rbits32(uint32_t k0, uint32_t k1, uint32_t idx) {
    uint32_t o0, o1;
    threefry2x32(k0, k1, 0u, idx, o0, o1);
    return o0 ^ o1;
}

__device__ __forceinline__ float bits_to_u01(uint32_t b) {
    return __uint_as_float((b >> 9) | 0x3f800000u) - 1.0f;
}

__device__ __forceinline__ float gumbel_draw(uint32_t k0, uint32_t k1, uint32_t idx,
                                             float mn, float span) {
    float u = bits_to_u01(rbits32(k0, k1, idx));
    u = fmaxf(mn, __fadd_rn(__fmul_rn(u, span), mn));
    return -logf(-logf(u));
}

// ---------------- packed f32x2 helpers ----------------
__device__ __forceinline__ unsigned long long packf2(float lo, float hi) {
    unsigned long long r;
    asm("mov.b64 %0, {%1, %2};" : "=l"(r) : "f"(lo), "f"(hi));
    return r;
}
__device__ __forceinline__ void unpackf2(unsigned long long v, float& lo, float& hi) {
    asm("mov.b64 {%0, %1}, %2;" : "=f"(lo), "=f"(hi) : "l"(v));
}
__device__ __forceinline__ void ffma2(unsigned long long& acc,
                                      unsigned long long a, unsigned long long b) {
    asm("fma.rn.f32x2 %0, %1, %2, %0;" : "+l"(acc) : "l"(a), "l"(b));
}

// ---------------- MLP chain (node-uniform GAT stack collapsed to [B,H]) ----------------
// 256 threads, 28 rows/block, warp tile r7 x c64 (R14 winner).
// Double-buffered Ws (2x64KB) + x (2x14KB): ONE barrier per layer, next-layer W
// fill issued before compute so LDG latency hides under the FMA/LDS stream.
#define BROWS 28
__global__ void __launch_bounds__(256) mlp_kernel(
    const float* __restrict__ noise, const float* __restrict__ w1,
    const float* __restrict__ b1, const float* __restrict__ gw,
    const float* __restrict__ gb) {
    __shared__ __align__(16) float Ws[2][HH * HH];    // 128 KB
    __shared__ __align__(16) float xsp[2][12 * 256];  // 24 KB
    __shared__ __align__(16) float xss[2][4 * HH];    // 4 KB
    const int tid = threadIdx.x;
    const int lane = tid & 31;
    const int w = tid >> 5;
    const int rg = w >> 1;              // 0..3
    const int cg = w & 1;               // 0..1
    const int c1 = cg * 64 + lane;
    const int c2 = c1 + 32;
    const int base = blockIdx.x * BROWS;

    // load input rows (noise) into grouped layout (buffer 0)
    for (int i = tid; i < BROWS * HH; i += 256) {
        int r = i >> 7, c = i & 127, g = base + r;
        float v = (g < BB) ? noise[g * HH + c] : 0.f;
        int rgi = r / 7, rel = r % 7;
        if (rel == 6) xss[0][rgi * HH + c] = v;
        else xsp[0][(rgi * 3 + (rel >> 1)) * 256 + c * 2 + (rel & 1)] = v;
    }
    // prologue: fill Ws[0] with layer-0 weights
    {
        const float4* wv = (const float4*)w1;
        float4* wd = (float4*)Ws[0];
        #pragma unroll
        for (int i = 0; i < 16; i++) wd[tid + i * 256] = wv[tid + i * 256];
    }

    float keep[14];                      // keep[rel*2+ci]
    #pragma unroll 1
    for (int layer = 0; layer <= LL; layer++) {
        const float* bsrc = (layer == 0) ? b1 : gb + (layer - 1) * HH;
        const int wb = layer & 1;
        const int xb = layer & 1;
        __syncthreads();   // Ws[wb] filled; x[xb] fully written

        // issue NEXT layer's W fill into the idle buffer (latency overlaps compute)
        if (layer < LL) {
            const float4* wv = (const float4*)(gw + (size_t)layer * HH * HH);
            float4* wd = (float4*)Ws[wb ^ 1];
            #pragma unroll
            for (int i = 0; i < 16; i++) wd[tid + i * 256] = wv[tid + i * 256];
        }

        const float* Wb = Ws[wb];
        const float bias1 = bsrc[c1];
        const float bias2 = bsrc[c2];
        unsigned long long accp[6];      // [p][ci]
        float acc61, acc62;
        #pragma unroll
        for (int p = 0; p < 3; p++) {
            accp[p * 2 + 0] = packf2(bias1, bias1);
            accp[p * 2 + 1] = packf2(bias2, bias2);
        }
        acc61 = bias1; acc62 = bias2;

        const float* xpb = &xsp[xb][(rg * 3) * 256];
        const float* xsc = &xss[xb][rg * HH];
        #pragma unroll 2
        for (int k = 0; k < HH; k += 4) {
            float wa0 = Wb[(k + 0) * HH + c1];
            float wa1 = Wb[(k + 1) * HH + c1];
            float wa2 = Wb[(k + 2) * HH + c1];
            float wa3 = Wb[(k + 3) * HH + c1];
            float wb0 = Wb[(k + 0) * HH + c2];
            float wb1 = Wb[(k + 1) * HH + c2];
            float wb2 = Wb[(k + 2) * HH + c2];
            float wb3 = Wb[(k + 3) * HH + c2];
            unsigned long long wa0p = packf2(wa0, wa0);
            unsigned long long wa1p = packf2(wa1, wa1);
            unsigned long long wa2p = packf2(wa2, wa2);
            unsigned long long wa3p = packf2(wa3, wa3);
            unsigned long long wb0p = packf2(wb0, wb0);
            unsigned long long wb1p = packf2(wb1, wb1);
            unsigned long long wb2p = packf2(wb2, wb2);
            unsigned long long wb3p = packf2(wb3, wb3);
            #pragma unroll
            for (int p = 0; p < 3; p++) {
                const ulonglong2 xa = *(const ulonglong2*)&xpb[p * 256 + k * 2];
                const ulonglong2 xbv = *(const ulonglong2*)&xpb[p * 256 + k * 2 + 4];
                ffma2(accp[p * 2 + 0], xa.x, wa0p);
                ffma2(accp[p * 2 + 0], xa.y, wa1p);
                ffma2(accp[p * 2 + 0], xbv.x, wa2p);
                ffma2(accp[p * 2 + 0], xbv.y, wa3p);
                ffma2(accp[p * 2 + 1], xa.x, wb0p);
                ffma2(accp[p * 2 + 1], xa.y, wb1p);
                ffma2(accp[p * 2 + 1], xbv.x, wb2p);
                ffma2(accp[p * 2 + 1], xbv.y, wb3p);
            }
            {
                const float4 xv = *(const float4*)&xsc[k];
                acc61 = fmaf(xv.x, wa0, acc61);
                acc61 = fmaf(xv.y, wa1, acc61);
                acc61 = fmaf(xv.z, wa2, acc61);
                acc61 = fmaf(xv.w, wa3, acc61);
                acc62 = fmaf(xv.x, wb0, acc62);
                acc62 = fmaf(xv.y, wb1, acc62);
                acc62 = fmaf(xv.z, wb2, acc62);
                acc62 = fmaf(xv.w, wb3, acc62);
            }
        }

        float av[14];
        #pragma unroll
        for (int p = 0; p < 3; p++) {
            unpackf2(accp[p * 2 + 0], av[(2 * p) * 2 + 0], av[(2 * p + 1) * 2 + 0]);
            unpackf2(accp[p * 2 + 1], av[(2 * p) * 2 + 1], av[(2 * p + 1) * 2 + 1]);
        }
        av[12] = acc61; av[13] = acc62;
        #pragma unroll
        for (int i = 0; i < 14; i++) {
            float v = (layer == 0) ? av[i] : av[i] + keep[i];
            keep[i] = fmaxf(v, 0.f);
        }
        if (layer < LL) {
            // write to the OTHER x buffer: no race with this layer's readers
            const int xn = xb ^ 1;
            #pragma unroll
            for (int p = 0; p < 3; p++) {
                *(float2*)&xsp[xn][(rg * 3 + p) * 256 + c1 * 2] =
                    make_float2(keep[(2 * p) * 2 + 0], keep[(2 * p + 1) * 2 + 0]);
                *(float2*)&xsp[xn][(rg * 3 + p) * 256 + c2 * 2] =
                    make_float2(keep[(2 * p) * 2 + 1], keep[(2 * p + 1) * 2 + 1]);
            }
            xss[xn][rg * HH + c1] = keep[12];
            xss[xn][rg * HH + c2] = keep[13];
        }
    }
    // final store: rows base + rg*7 + rel, cols c1/c2
    #pragma unroll
    for (int rel = 0; rel < 7; rel++) {
        int g = base + rg * 7 + rel;
        if (g < BB) {
            d_X[(size_t)g * HH + c1] = keep[rel * 2 + 0];
            d_X[(size_t)g * HH + c2] = keep[rel * 2 + 1];
        }
    }
}

// ---------------- Heads: 128 threads = 2 batches x 2 warps ----------------
// R8-exact numerics; nf stores now staged in smem and written coalesced.
__global__ void __launch_bounds__(128) heads_kernel(
    const float* __restrict__ w_atom, const float* __restrict__ b_atom,
    const float* __restrict__ w_hyb,  const float* __restrict__ b_hyb,
    const float* __restrict__ w_deg,  const float* __restrict__ b_deg,
    const float* __restrict__ w_chg,  const float* __restrict__ b_chg,
    const float* __restrict__ w_arom, const float* __restrict__ b_arom,
    const float* __restrict__ w_eex,  const float* __restrict__ b_eex,
    const float* __restrict__ w_ety,  const float* __restrict__ b_ety,
    uint32_t a_k0, uint32_t a_k1, uint32_t h_k0, uint32_t h_k1,
    uint32_t r_k0, uint32_t r_k1, uint32_t e_k0, uint32_t e_k1,
    float mn, float span,
    float* __restrict__ out) {
    __shared__ __align__(16) float xvs[2][HH];
    __shared__ __align__(16) float wa[HH * AA];
    __shared__ __align__(16) float wh[HH * HYBN];
    __shared__ __align__(16) float wdg[HH], wcg[HH], wrg[HH];
    __shared__ __align__(16) float wts[136];
    __shared__ __align__(16) float wes[34];
    __shared__ float nfs[2][NN][17];
    __shared__ float wsum[2][2][2];     // [pair][warp][alp/hlp]

    const int tid = threadIdx.x;
    const int wid = tid >> 5;           // 0..3
    const int lane = tid & 31;
    const int pair = wid >> 1;          // batch within block (0/1)
    const int pw = wid & 1;             // warp within pair

    for (int i = tid; i < HH * AA; i += 128) wa[i] = w_atom[i];
    for (int i = tid; i < HH * HYBN; i += 128) wh[i] = w_hyb[i];
    if (tid < HH) { wdg[tid] = w_deg[tid]; wcg[tid] = w_chg[tid]; wrg[tid] = w_arom[tid]; }
    if (tid < 34) wes[tid] = w_eex[tid];
    for (int i = tid; i < 136; i += 128) wts[i] = w_ety[i];
    __syncthreads();   // single block sync: weight staging

    const int b = blockIdx.x * 2 + pair;

    // both warps of a pair redundantly load the full x row
    ((float4*)xvs[pair])[lane] = ((const float4*)(d_X + (size_t)b * HH))[lane];
    __syncwarp();

    // ---- dots: 16 outputs x 2 lanes, 64 k each ----
    const int o = lane >> 1;
    const int part = lane & 1;
    const float* wp; int stride; float bias;
    if (o < AA)       { wp = wa + o;        stride = AA;   bias = b_atom[o]; }
    else if (o < 13)  { wp = wh + (o - 10); stride = HYBN; bias = b_hyb[o - 10]; }
    else if (o == 13) { wp = wdg;           stride = 1;    bias = b_deg[0]; }
    else if (o == 14) { wp = wcg;           stride = 1;    bias = b_chg[0]; }
    else              { wp = wrg;           stride = 1;    bias = b_arom[0]; }
    float acc = 0.f;
    {
        const int k0 = part * 64;
        const float* xp = xvs[pair];
        #pragma unroll 8
        for (int k = 0; k < 64; k++)
            acc = fmaf(xp[k0 + k], wp[(k0 + k) * stride], acc);
    }
    acc += __shfl_xor_sync(0xffffffffu, acc, 1);
    const float logit = acc + bias;

    // gather all logits from even lanes
    float alog[AA], hlog[HYBN];
    #pragma unroll
    for (int a = 0; a < AA; a++) alog[a] = __shfl_sync(0xffffffffu, logit, 2 * a);
    #pragma unroll
    for (int a = 0; a < HYBN; a++) hlog[a] = __shfl_sync(0xffffffffu, logit, 20 + 2 * a);
    const float dlg = __shfl_sync(0xffffffffu, logit, 26);
    const float clg = __shfl_sync(0xffffffffu, logit, 28);
    const float rlg = __shfl_sync(0xffffffffu, logit, 30);
    const float sdeg = 1.f / (1.f + expf(-dlg));
    const float schg = tanhf(clg);
    const float sarom = 1.f / (1.f + expf(-rlg));

    // ---- log-softmax constants (same serial order as R2/R5) ----
    float m = alog[0];
    #pragma unroll
    for (int a = 1; a < AA; a++) m = fmaxf(m, alog[a]);
    float s = 0.f;
    #pragma unroll
    for (int a = 0; a < AA; a++) s += expf(alog[a] - m);
    const float malse_a = m + logf(s);
    float m2 = hlog[0];
    #pragma unroll
    for (int a = 1; a < HYBN; a++) m2 = fmaxf(m2, hlog[a]);
    float s2 = 0.f;
    #pragma unroll
    for (int a = 0; a < HYBN; a++) s2 += expf(hlog[a] - m2);
    const float malse_h = m2 + logf(s2);

    // ---- node phase: 2 lanes per node; warp pw handles nodes pw*16..pw*16+15 ----
    const int n = pw * 16 + (lane >> 1);
    const int h = lane & 1;
    const uint32_t node = (uint32_t)(b * NN + n);

    int ai = h * 5;
    float best = -3.4e38f, alsel = 0.f;
    #pragma unroll
    for (int j = 0; j < 5; j++) {
        int a = h * 5 + j;
        float g = gumbel_draw(a_k0, a_k1, node * AA + a, mn, span);
        float v = alog[a] + g;
        if (v > best) { best = v; ai = a; alsel = alog[a]; }
    }
    {
        float ob = __shfl_xor_sync(0xffffffffu, best, 1);
        int   oi = __shfl_xor_sync(0xffffffffu, ai, 1);
        float oa = __shfl_xor_sync(0xffffffffu, alsel, 1);
        if (ob > best || (ob == best && oi < ai)) { best = ob; ai = oi; alsel = oa; }
    }
    int hi = (h == 0) ? 0 : 2;
    float bh = -3.4e38f, hlsel;
    if (h == 0) {
        hlsel = hlog[0];
        #pragma unroll
        for (int a = 0; a < 2; a++) {
            float g = gumbel_draw(h_k0, h_k1, node * HYBN + a, mn, span);
            float v = hlog[a] + g;
            if (v > bh) { bh = v; hi = a; hlsel = hlog[a]; }
        }
    } else {
        float g = gumbel_draw(h_k0, h_k1, node * HYBN + 2, mn, span);
        bh = hlog[2] + g;
        hlsel = hlog[2];
    }
    {
        float ob = __shfl_xor_sync(0xffffffffu, bh, 1);
        int   oi = __shfl_xor_sync(0xffffffffu, hi, 1);
        float oh2 = __shfl_xor_sync(0xffffffffu, hlsel, 1);
        if (ob > bh || (ob == bh && oi < hi)) { bh = ob; hi = oi; hlsel = oh2; }
    }
    float u = 0.f;
    if (h == 1) u = bits_to_u01(rbits32(r_k0, r_k1, node));
    u = __shfl_xor_sync(0xffffffffu, u, 1);

    float myalp = 0.f, myhlp = 0.f;
    if (h == 0) {
        const float arom = (u < sarom) ? 1.f : 0.f;
        const float val = c_maxval[ai] / 5.0f;
        // stage nf row in smem only (coalesced global store after barrier)
        #pragma unroll
        for (int f = 0; f < AA; f++) nfs[pair][n][f] = (f == ai) ? 1.f : 0.f;
        nfs[pair][n][10] = sdeg;
        nfs[pair][n][11] = schg;
        #pragma unroll
        for (int f = 0; f < HYBN; f++) nfs[pair][n][12 + f] = (f == hi) ? 1.f : 0.f;
        nfs[pair][n][15] = arom;
        nfs[pair][n][16] = val;
        myalp = alsel - malse_a;
        myhlp = hlsel - malse_h;
    }
    #pragma unroll
    for (int off = 16; off > 0; off >>= 1) {
        myalp += __shfl_down_sync(0xffffffffu, myalp, off);
        myhlp += __shfl_down_sync(0xffffffffu, myhlp, off);
    }
    if (lane == 0) { wsum[pair][pw][0] = myalp; wsum[pair][pw][1] = myhlp; }

    // named barrier over this pair's 64 threads (nf + wsum ready)
    asm volatile("bar.sync %0, 64;" :: "r"(1 + pair) : "memory");

    if (pw == 0 && lane == 0) {
        out[ALP_OFF + b] = (wsum[pair][0][0] + wsum[pair][1][0]) / 32.f;
        out[HLP_OFF + b] = (wsum[pair][0][1] + wsum[pair][1][1]) / 32.f;
    }

    // ---- coalesced nf store: 544 contiguous floats at out + b*544 ----
    {
        const float* nf_flat = &nfs[pair][0][0];
        float* onf = out + NF_OFF + (size_t)b * (NN * 17);
        const int tid2 = pw * 32 + lane;
        #pragma unroll
        for (int i = tid2; i < NN * 17; i += 64) onf[i] = nf_flat[i];
    }

    // ---- edge phase: 1 edge per lane across the pair's 64 threads ----
    const int e = pw * 32 + lane;
    if (e < NE) {
        const int un = (e < 31) ? e : e - 30;       // eu
        const int vn = (e < 31) ? e + 1 : e - 31;   // ev
        float elog = b_eex[0];
        float tl[4];
        #pragma unroll
        for (int t = 0; t < 4; t++) tl[t] = b_ety[t];
        #pragma unroll
        for (int f = 0; f < 17; f++) {
            float a1 = nfs[pair][un][f];
            float a2 = nfs[pair][vn][f];
            elog = fmaf(a1, wes[f], elog);
            elog = fmaf(a2, wes[17 + f], elog);
            #pragma unroll
            for (int t = 0; t < 4; t++) {
                tl[t] = fmaf(a1, wts[f * 4 + t], tl[t]);
                tl[t] = fmaf(a2, wts[(17 + f) * 4 + t], tl[t]);
            }
        }
        float p = 1.f / (1.f + expf(-elog));
        out[EMASK_OFF + (size_t)b * NE + e] = (p > 0.5f) ? 1.f : 0.f;

        const uint32_t ebase = (uint32_t)(b * NE + e) * 4u;
        int ti = 0; float bt = -1e30f;
        #pragma unroll
        for (int t = 0; t < 4; t++) {
            float g = gumbel_draw(e_k0, e_k1, ebase + t, mn, span);
            float v = tl[t] + g;
            if (v > bt) { bt = v; ti = t; }
        }
        float4 oh;
        oh.x = (ti == 0) ? 1.f : 0.f;
        oh.y = (ti == 1) ? 1.f : 0.f;
        oh.z = (ti == 2) ? 1.f : 0.f;
        oh.w = (ti == 3) ? 1.f : 0.f;
        *(float4*)(out + EATTR_OFF + (size_t)ebase) = oh;
    }
}

// ---------------- launch ----------------
extern "C" void kernel_launch(void* const* d_in, const int* in_sizes, int n_in,
                              void* d_out, int out_size) {
    const float* noise  = (const float*)d_in[0];
    const float* w1     = (const float*)d_in[1];
    const float* b1     = (const float*)d_in[2];
    const float* gat_w  = (const float*)d_in[3];
    const float* gat_b  = (const float*)d_in[4];
    // d_in[5] att_src, d_in[6] att_dst: numerically irrelevant (node-uniform collapse)
    const float* w_atom = (const float*)d_in[7];
    const float* b_atom = (const float*)d_in[8];
    const float* w_hyb  = (const float*)d_in[9];
    const float* b_hyb  = (const float*)d_in[10];
    const float* w_deg  = (const float*)d_in[11];
    const float* b_deg  = (const float*)d_in[12];
    const float* w_chg  = (const float*)d_in[13];
    const float* b_chg  = (const float*)d_in[14];
    const float* w_arom = (const float*)d_in[15];
    const float* b_arom = (const float*)d_in[16];
    const float* w_eex  = (const float*)d_in[17];
    const float* b_eex  = (const float*)d_in[18];
    const float* w_ety  = (const float*)d_in[19];
    const float* b_ety  = (const float*)d_in[20];
    float* out = (float*)d_out;

    // jax.random.key(42) -> (0, 42); partitionable split: sk[i] = threefry(key,(0,i))
    uint32_t sk[4][2];
    for (uint32_t i = 0; i < 4; i++)
        threefry2x32(0u, 42u, 0u, i, sk[i][0], sk[i][1]);

    const float mn = 1e-6f;
    const float mx = (float)(1.0 - 1e-6);
    const float span = mx - mn;

    mlp_kernel<<<(BB + BROWS - 1) / BROWS, 256>>>(noise, w1, b1, gat_w, gat_b);

    heads_kernel<<<BB / 2, 128>>>(w_atom, b_atom, w_hyb, b_hyb, w_deg, b_deg,
                                  w_chg, b_chg, w_arom, b_arom, w_eex, b_eex,
                                  w_ety, b_ety,
                                  sk[0][0], sk[0][1], sk[1][0], sk[1][1],
                                  sk[2][0], sk[2][1], sk[3][0], sk[3][1],
                                  mn, span, out);
}

// round 16
// speedup vs baseline: 1.3385x; 1.0552x over previous
#include <cuda_runtime.h>
#include <cstdint>

#define BB 4096
#define NN 32
#define HH 128
#define LL 16
#define AA 10
#define HYBN 3
#define NE 62

// output layout: tuple flattened in return order, float32
#define NF_OFF    0
#define ALP_OFF   (BB*NN*17)              // 2228224
#define HLP_OFF   (ALP_OFF + BB)          // 2232320
#define EATTR_OFF (HLP_OFF + BB)          // 2236416
#define EMASK_OFF (EATTR_OFF + BB*NE*4)   // 3252224

// scratch (__device__ global: allocation-free)
__device__ __align__(16) float d_X[BB*HH];

__constant__ float c_maxval[AA] = {4.f,3.f,2.f,1.f,4.f,2.f,6.f,1.f,4.f,4.f};

// ---------------- Threefry-2x32 (exact JAX implementation) ----------------
__host__ __device__ __forceinline__ uint32_t rotl32(uint32_t x, int d) {
    return (x << d) | (x >> (32 - d));
}
__host__ __device__ __forceinline__ void threefry2x32(uint32_t k0, uint32_t k1,
                                                      uint32_t x0, uint32_t x1,
                                                      uint32_t& o0, uint32_t& o1) {
    uint32_t ks2 = k0 ^ k1 ^ 0x1BD11BDAu;
#define TFR(r) { x0 += x1; x1 = rotl32(x1, (r)); x1 ^= x0; }
    x0 += k0; x1 += k1;
    TFR(13) TFR(15) TFR(26) TFR(6)   x0 += k1;  x1 += ks2 + 1u;
    TFR(17) TFR(29) TFR(16) TFR(24)  x0 += ks2; x1 += k0 + 2u;
    TFR(13) TFR(15) TFR(26) TFR(6)   x0 += k0;  x1 += k1 + 3u;
    TFR(17) TFR(29) TFR(16) TFR(24)  x0 += k1;  x1 += ks2 + 4u;
    TFR(13) TFR(15) TFR(26) TFR(6)   x0 += ks2; x1 += k0 + 5u;
#undef TFR
    o0 = x0; o1 = x1;
}

__device__ __forceinline__ uint32_t rbits32(uint32_t k0, uint32_t k1, uint32_t idx) {
    uint32_t o0, o1;
    threefry2x32(k0, k1, 0u, idx, o0, o1);
    return o0 ^ o1;
}

__device__ __forceinline__ float bits_to_u01(uint32_t b) {
    return __uint_as_float((b >> 9) | 0x3f800000u) - 1.0f;
}

__device__ __forceinline__ float gumbel_draw(uint32_t k0, uint32_t k1, uint32_t idx,
                                             float mn, float span) {
    float u = bits_to_u01(rbits32(k0, k1, idx));
    u = fmaxf(mn, __fadd_rn(__fmul_rn(u, span), mn));
    return -logf(-logf(u));
}

// ---------------- packed f32x2 helpers ----------------
__device__ __forceinline__ unsigned long long packf2(float lo, float hi) {
    unsigned long long r;
    asm("mov.b64 %0, {%1, %2};" : "=l"(r) : "f"(lo), "f"(hi));
    return r;
}
__device__ __forceinline__ void unpackf2(unsigned long long v, float& lo, float& hi) {
    asm("mov.b64 {%0, %1}, %2;" : "=f"(lo), "=f"(hi) : "l"(v));
}
__device__ __forceinline__ void ffma2(unsigned long long& acc,
                                      unsigned long long a, unsigned long long b) {
    asm("fma.rn.f32x2 %0, %1, %2, %0;" : "+l"(acc) : "l"(a), "l"(b));
}

// ---------------- MLP chain (node-uniform GAT stack collapsed to [B,H]) ----------------
// R15-exact: 256 threads, 28 rows/block, warp tile r7 x c64, double-buffered Ws+x,
// ONE barrier per layer, next-layer W fill overlapped with compute.
#define BROWS 28
__global__ void __launch_bounds__(256) mlp_kernel(
    const float* __restrict__ noise, const float* __restrict__ w1,
    const float* __restrict__ b1, const float* __restrict__ gw,
    const float* __restrict__ gb) {
    __shared__ __align__(16) float Ws[2][HH * HH];    // 128 KB
    __shared__ __align__(16) float xsp[2][12 * 256];  // 24 KB
    __shared__ __align__(16) float xss[2][4 * HH];    // 4 KB
    const int tid = threadIdx.x;
    const int lane = tid & 31;
    const int w = tid >> 5;
    const int rg = w >> 1;              // 0..3
    const int cg = w & 1;               // 0..1
    const int c1 = cg * 64 + lane;
    const int c2 = c1 + 32;
    const int base = blockIdx.x * BROWS;

    // load input rows (noise) into grouped layout (buffer 0)
    for (int i = tid; i < BROWS * HH; i += 256) {
        int r = i >> 7, c = i & 127, g = base + r;
        float v = (g < BB) ? noise[g * HH + c] : 0.f;
        int rgi = r / 7, rel = r % 7;
        if (rel == 6) xss[0][rgi * HH + c] = v;
        else xsp[0][(rgi * 3 + (rel >> 1)) * 256 + c * 2 + (rel & 1)] = v;
    }
    // prologue: fill Ws[0] with layer-0 weights
    {
        const float4* wv = (const float4*)w1;
        float4* wd = (float4*)Ws[0];
        #pragma unroll
        for (int i = 0; i < 16; i++) wd[tid + i * 256] = wv[tid + i * 256];
    }

    float keep[14];                      // keep[rel*2+ci]
    #pragma unroll 1
    for (int layer = 0; layer <= LL; layer++) {
        const float* bsrc = (layer == 0) ? b1 : gb + (layer - 1) * HH;
        const int wb = layer & 1;
        const int xb = layer & 1;
        __syncthreads();   // Ws[wb] filled; x[xb] fully written

        // issue NEXT layer's W fill into the idle buffer (latency overlaps compute)
        if (layer < LL) {
            const float4* wv = (const float4*)(gw + (size_t)layer * HH * HH);
            float4* wd = (float4*)Ws[wb ^ 1];
            #pragma unroll
            for (int i = 0; i < 16; i++) wd[tid + i * 256] = wv[tid + i * 256];
        }

        const float* Wb = Ws[wb];
        const float bias1 = bsrc[c1];
        const float bias2 = bsrc[c2];
        unsigned long long accp[6];      // [p][ci]
        float acc61, acc62;
        #pragma unroll
        for (int p = 0; p < 3; p++) {
            accp[p * 2 + 0] = packf2(bias1, bias1);
            accp[p * 2 + 1] = packf2(bias2, bias2);
        }
        acc61 = bias1; acc62 = bias2;

        const float* xpb = &xsp[xb][(rg * 3) * 256];
        const float* xsc = &xss[xb][rg * HH];
        #pragma unroll 2
        for (int k = 0; k < HH; k += 4) {
            float wa0 = Wb[(k + 0) * HH + c1];
            float wa1 = Wb[(k + 1) * HH + c1];
            float wa2 = Wb[(k + 2) * HH + c1];
            float wa3 = Wb[(k + 3) * HH + c1];
            float wb0 = Wb[(k + 0) * HH + c2];
            float wb1 = Wb[(k + 1) * HH + c2];
            float wb2 = Wb[(k + 2) * HH + c2];
            float wb3 = Wb[(k + 3) * HH + c2];
            unsigned long long wa0p = packf2(wa0, wa0);
            unsigned long long wa1p = packf2(wa1, wa1);
            unsigned long long wa2p = packf2(wa2, wa2);
            unsigned long long wa3p = packf2(wa3, wa3);
            unsigned long long wb0p = packf2(wb0, wb0);
            unsigned long long wb1p = packf2(wb1, wb1);
            unsigned long long wb2p = packf2(wb2, wb2);
            unsigned long long wb3p = packf2(wb3, wb3);
            #pragma unroll
            for (int p = 0; p < 3; p++) {
                const ulonglong2 xa = *(const ulonglong2*)&xpb[p * 256 + k * 2];
                const ulonglong2 xbv = *(const ulonglong2*)&xpb[p * 256 + k * 2 + 4];
                ffma2(accp[p * 2 + 0], xa.x, wa0p);
                ffma2(accp[p * 2 + 0], xa.y, wa1p);
                ffma2(accp[p * 2 + 0], xbv.x, wa2p);
                ffma2(accp[p * 2 + 0], xbv.y, wa3p);
                ffma2(accp[p * 2 + 1], xa.x, wb0p);
                ffma2(accp[p * 2 + 1], xa.y, wb1p);
                ffma2(accp[p * 2 + 1], xbv.x, wb2p);
                ffma2(accp[p * 2 + 1], xbv.y, wb3p);
            }
            {
                const float4 xv = *(const float4*)&xsc[k];
                acc61 = fmaf(xv.x, wa0, acc61);
                acc61 = fmaf(xv.y, wa1, acc61);
                acc61 = fmaf(xv.z, wa2, acc61);
                acc61 = fmaf(xv.w, wa3, acc61);
                acc62 = fmaf(xv.x, wb0, acc62);
                acc62 = fmaf(xv.y, wb1, acc62);
                acc62 = fmaf(xv.z, wb2, acc62);
                acc62 = fmaf(xv.w, wb3, acc62);
            }
        }

        float av[14];
        #pragma unroll
        for (int p = 0; p < 3; p++) {
            unpackf2(accp[p * 2 + 0], av[(2 * p) * 2 + 0], av[(2 * p + 1) * 2 + 0]);
            unpackf2(accp[p * 2 + 1], av[(2 * p) * 2 + 1], av[(2 * p + 1) * 2 + 1]);
        }
        av[12] = acc61; av[13] = acc62;
        #pragma unroll
        for (int i = 0; i < 14; i++) {
            float v = (layer == 0) ? av[i] : av[i] + keep[i];
            keep[i] = fmaxf(v, 0.f);
        }
        if (layer < LL) {
            // write to the OTHER x buffer: no race with this layer's readers
            const int xn = xb ^ 1;
            #pragma unroll
            for (int p = 0; p < 3; p++) {
                *(float2*)&xsp[xn][(rg * 3 + p) * 256 + c1 * 2] =
                    make_float2(keep[(2 * p) * 2 + 0], keep[(2 * p + 1) * 2 + 0]);
                *(float2*)&xsp[xn][(rg * 3 + p) * 256 + c2 * 2] =
                    make_float2(keep[(2 * p) * 2 + 1], keep[(2 * p + 1) * 2 + 1]);
            }
            xss[xn][rg * HH + c1] = keep[12];
            xss[xn][rg * HH + c2] = keep[13];
        }
    }
    // final store: rows base + rg*7 + rel, cols c1/c2
    #pragma unroll
    for (int rel = 0; rel < 7; rel++) {
        int g = base + rg * 7 + rel;
        if (g < BB) {
            d_X[(size_t)g * HH + c1] = keep[rel * 2 + 0];
            d_X[(size_t)g * HH + c2] = keep[rel * 2 + 1];
        }
    }
}

// ---------------- Heads: 128 threads = 2 batches x 2 warps ----------------
// R15 numerics; named pair-barriers replaced by __syncthreads to use only ONE
// HW barrier per CTA (barrier pool was capping residency at ~5 CTAs/SM).
__global__ void __launch_bounds__(128) heads_kernel(
    const float* __restrict__ w_atom, const float* __restrict__ b_atom,
    const float* __restrict__ w_hyb,  const float* __restrict__ b_hyb,
    const float* __restrict__ w_deg,  const float* __restrict__ b_deg,
    const float* __restrict__ w_chg,  const float* __restrict__ b_chg,
    const float* __restrict__ w_arom, const float* __restrict__ b_arom,
    const float* __restrict__ w_eex,  const float* __restrict__ b_eex,
    const float* __restrict__ w_ety,  const float* __restrict__ b_ety,
    uint32_t a_k0, uint32_t a_k1, uint32_t h_k0, uint32_t h_k1,
    uint32_t r_k0, uint32_t r_k1, uint32_t e_k0, uint32_t e_k1,
    float mn, float span,
    float* __restrict__ out) {
    __shared__ __align__(16) float xvs[2][HH];
    __shared__ __align__(16) float wa[HH * AA];
    __shared__ __align__(16) float wh[HH * HYBN];
    __shared__ __align__(16) float wdg[HH], wcg[HH], wrg[HH];
    __shared__ __align__(16) float wts[136];
    __shared__ __align__(16) float wes[34];
    __shared__ float nfs[2][NN][17];
    __shared__ float wsum[2][2][2];     // [pair][warp][alp/hlp]

    const int tid = threadIdx.x;
    const int wid = tid >> 5;           // 0..3
    const int lane = tid & 31;
    const int pair = wid >> 1;          // batch within block (0/1)
    const int pw = wid & 1;             // warp within pair

    for (int i = tid; i < HH * AA; i += 128) wa[i] = w_atom[i];
    for (int i = tid; i < HH * HYBN; i += 128) wh[i] = w_hyb[i];
    if (tid < HH) { wdg[tid] = w_deg[tid]; wcg[tid] = w_chg[tid]; wrg[tid] = w_arom[tid]; }
    if (tid < 34) wes[tid] = w_eex[tid];
    for (int i = tid; i < 136; i += 128) wts[i] = w_ety[i];
    __syncthreads();   // weight staging

    const int b = blockIdx.x * 2 + pair;

    // both warps of a pair redundantly load the full x row
    ((float4*)xvs[pair])[lane] = ((const float4*)(d_X + (size_t)b * HH))[lane];
    __syncwarp();

    // ---- dots: 16 outputs x 2 lanes, 64 k each ----
    const int o = lane >> 1;
    const int part = lane & 1;
    const float* wp; int stride; float bias;
    if (o < AA)       { wp = wa + o;        stride = AA;   bias = b_atom[o]; }
    else if (o < 13)  { wp = wh + (o - 10); stride = HYBN; bias = b_hyb[o - 10]; }
    else if (o == 13) { wp = wdg;           stride = 1;    bias = b_deg[0]; }
    else if (o == 14) { wp = wcg;           stride = 1;    bias = b_chg[0]; }
    else              { wp = wrg;           stride = 1;    bias = b_arom[0]; }
    float acc = 0.f;
    {
        const int k0 = part * 64;
        const float* xp = xvs[pair];
        #pragma unroll 8
        for (int k = 0; k < 64; k++)
            acc = fmaf(xp[k0 + k], wp[(k0 + k) * stride], acc);
    }
    acc += __shfl_xor_sync(0xffffffffu, acc, 1);
    const float logit = acc + bias;

    // gather all logits from even lanes
    float alog[AA], hlog[HYBN];
    #pragma unroll
    for (int a = 0; a < AA; a++) alog[a] = __shfl_sync(0xffffffffu, logit, 2 * a);
    #pragma unroll
    for (int a = 0; a < HYBN; a++) hlog[a] = __shfl_sync(0xffffffffu, logit, 20 + 2 * a);
    const float dlg = __shfl_sync(0xffffffffu, logit, 26);
    const float clg = __shfl_sync(0xffffffffu, logit, 28);
    const float rlg = __shfl_sync(0xffffffffu, logit, 30);
    const float sdeg = 1.f / (1.f + expf(-dlg));
    const float schg = tanhf(clg);
    const float sarom = 1.f / (1.f + expf(-rlg));

    // ---- log-softmax constants (same serial order as R2/R5) ----
    float m = alog[0];
    #pragma unroll
    for (int a = 1; a < AA; a++) m = fmaxf(m, alog[a]);
    float s = 0.f;
    #pragma unroll
    for (int a = 0; a < AA; a++) s += expf(alog[a] - m);
    const float malse_a = m + logf(s);
    float m2 = hlog[0];
    #pragma unroll
    for (int a = 1; a < HYBN; a++) m2 = fmaxf(m2, hlog[a]);
    float s2 = 0.f;
    #pragma unroll
    for (int a = 0; a < HYBN; a++) s2 += expf(hlog[a] - m2);
    const float malse_h = m2 + logf(s2);

    // ---- node phase: 2 lanes per node; warp pw handles nodes pw*16..pw*16+15 ----
    const int n = pw * 16 + (lane >> 1);
    const int h = lane & 1;
    const uint32_t node = (uint32_t)(b * NN + n);

    int ai = h * 5;
    float best = -3.4e38f, alsel = 0.f;
    #pragma unroll
    for (int j = 0; j < 5; j++) {
        int a = h * 5 + j;
        float g = gumbel_draw(a_k0, a_k1, node * AA + a, mn, span);
        float v = alog[a] + g;
        if (v > best) { best = v; ai = a; alsel = alog[a]; }
    }
    {
        float ob = __shfl_xor_sync(0xffffffffu, best, 1);
        int   oi = __shfl_xor_sync(0xffffffffu, ai, 1);
        float oa = __shfl_xor_sync(0xffffffffu, alsel, 1);
        if (ob > best || (ob == best && oi < ai)) { best = ob; ai = oi; alsel = oa; }
    }
    int hi = (h == 0) ? 0 : 2;
    float bh = -3.4e38f, hlsel;
    if (h == 0) {
        hlsel = hlog[0];
        #pragma unroll
        for (int a = 0; a < 2; a++) {
            float g = gumbel_draw(h_k0, h_k1, node * HYBN + a, mn, span);
            float v = hlog[a] + g;
            if (v > bh) { bh = v; hi = a; hlsel = hlog[a]; }
        }
    } else {
        float g = gumbel_draw(h_k0, h_k1, node * HYBN + 2, mn, span);
        bh = hlog[2] + g;
        hlsel = hlog[2];
    }
    {
        float ob = __shfl_xor_sync(0xffffffffu, bh, 1);
        int   oi = __shfl_xor_sync(0xffffffffu, hi, 1);
        float oh2 = __shfl_xor_sync(0xffffffffu, hlsel, 1);
        if (ob > bh || (ob == bh && oi < hi)) { bh = ob; hi = oi; hlsel = oh2; }
    }
    float u = 0.f;
    if (h == 1) u = bits_to_u01(rbits32(r_k0, r_k1, node));
    u = __shfl_xor_sync(0xffffffffu, u, 1);

    float myalp = 0.f, myhlp = 0.f;
    if (h == 0) {
        const float arom = (u < sarom) ? 1.f : 0.f;
        const float val = c_maxval[ai] / 5.0f;
        // stage nf row in smem only (coalesced global store after barrier)
        #pragma unroll
        for (int f = 0; f < AA; f++) nfs[pair][n][f] = (f == ai) ? 1.f : 0.f;
        nfs[pair][n][10] = sdeg;
        nfs[pair][n][11] = schg;
        #pragma unroll
        for (int f = 0; f < HYBN; f++) nfs[pair][n][12 + f] = (f == hi) ? 1.f : 0.f;
        nfs[pair][n][15] = arom;
        nfs[pair][n][16] = val;
        myalp = alsel - malse_a;
        myhlp = hlsel - malse_h;
    }
    #pragma unroll
    for (int off = 16; off > 0; off >>= 1) {
        myalp += __shfl_down_sync(0xffffffffu, myalp, off);
        myhlp += __shfl_down_sync(0xffffffffu, myhlp, off);
    }
    if (lane == 0) { wsum[pair][pw][0] = myalp; wsum[pair][pw][1] = myhlp; }

    // block barrier (single HW barrier): nfs + wsum of BOTH pairs ready
    __syncthreads();

    if (pw == 0 && lane == 0) {
        out[ALP_OFF + b] = (wsum[pair][0][0] + wsum[pair][1][0]) / 32.f;
        out[HLP_OFF + b] = (wsum[pair][0][1] + wsum[pair][1][1]) / 32.f;
    }

    // ---- coalesced nf store: 544 contiguous floats at out + b*544 ----
    {
        const float* nf_flat = &nfs[pair][0][0];
        float* onf = out + NF_OFF + (size_t)b * (NN * 17);
        const int tid2 = pw * 32 + lane;
        #pragma unroll
        for (int i = tid2; i < NN * 17; i += 64) onf[i] = nf_flat[i];
    }

    // ---- edge phase: 1 edge per lane across the pair's 64 threads ----
    const int e = pw * 32 + lane;
    if (e < NE) {
        const int un = (e < 31) ? e : e - 30;       // eu
        const int vn = (e < 31) ? e + 1 : e - 31;   // ev
        float elog = b_eex[0];
        float tl[4];
        #pragma unroll
        for (int t = 0; t < 4; t++) tl[t] = b_ety[t];
        #pragma unroll
        for (int f = 0; f < 17; f++) {
            float a1 = nfs[pair][un][f];
            float a2 = nfs[pair][vn][f];
            elog = fmaf(a1, wes[f], elog);
            elog = fmaf(a2, wes[17 + f], elog);
            #pragma unroll
            for (int t = 0; t < 4; t++) {
                tl[t] = fmaf(a1, wts[f * 4 + t], tl[t]);
                tl[t] = fmaf(a2, wts[(17 + f) * 4 + t], tl[t]);
            }
        }
        float p = 1.f / (1.f + expf(-elog));
        out[EMASK_OFF + (size_t)b * NE + e] = (p > 0.5f) ? 1.f : 0.f;

        const uint32_t ebase = (uint32_t)(b * NE + e) * 4u;
        int ti = 0; float bt = -1e30f;
        #pragma unroll
        for (int t = 0; t < 4; t++) {
            float g = gumbel_draw(e_k0, e_k1, ebase + t, mn, span);
            float v = tl[t] + g;
            if (v > bt) { bt = v; ti = t; }
        }
        float4 oh;
        oh.x = (ti == 0) ? 1.f : 0.f;
        oh.y = (ti == 1) ? 1.f : 0.f;
        oh.z = (ti == 2) ? 1.f : 0.f;
        oh.w = (ti == 3) ? 1.f : 0.f;
        *(float4*)(out + EATTR_OFF + (size_t)ebase) = oh;
    }
}

// ---------------- launch ----------------
extern "C" void kernel_launch(void* const* d_in, const int* in_sizes, int n_in,
                              void* d_out, int out_size) {
    const float* noise  = (const float*)d_in[0];
    const float* w1     = (const float*)d_in[1];
    const float* b1     = (const float*)d_in[2];
    const float* gat_w  = (const float*)d_in[3];
    const float* gat_b  = (const float*)d_in[4];
    // d_in[5] att_src, d_in[6] att_dst: numerically irrelevant (node-uniform collapse)
    const float* w_atom = (const float*)d_in[7];
    const float* b_atom = (const float*)d_in[8];
    const float* w_hyb  = (const float*)d_in[9];
    const float* b_hyb  = (const float*)d_in[10];
    const float* w_deg  = (const float*)d_in[11];
    const float* b_deg  = (const float*)d_in[12];
    const float* w_chg  = (const float*)d_in[13];
    const float* b_chg  = (const float*)d_in[14];
    const float* w_arom = (const float*)d_in[15];
    const float* b_arom = (const float*)d_in[16];
    const float* w_eex  = (const float*)d_in[17];
    const float* b_eex  = (const float*)d_in[18];
    const float* w_ety  = (const float*)d_in[19];
    const float* b_ety  = (const float*)d_in[20];
    float* out = (float*)d_out;

    // jax.random.key(42) -> (0, 42); partitionable split: sk[i] = threefry(key,(0,i))
    uint32_t sk[4][2];
    for (uint32_t i = 0; i < 4; i++)
        threefry2x32(0u, 42u, 0u, i, sk[i][0], sk[i][1]);

    const float mn = 1e-6f;
    const float mx = (float)(1.0 - 1e-6);
    const float span = mx - mn;

    mlp_kernel<<<(BB + BROWS - 1) / BROWS, 256>>>(noise, w1, b1, gat_w, gat_b);

    heads_kernel<<<BB / 2, 128>>>(w_atom, b_atom, w_hyb, b_hyb, w_deg, b_deg,
                                  w_chg, b_chg, w_arom, b_arom, w_eex, b_eex,
                                  w_ety, b_ety,
                                  sk[0][0], sk[0][1], sk[1][0], sk[1][1],
                                  sk[2][0], sk[2][1], sk[3][0], sk[3][1],
                                  mn, span, out);
}